// round 1
// baseline (speedup 1.0000x reference)
#include <cuda_runtime.h>
#include <math.h>

#define FULLMASK 0xFFFFFFFFu

// 2*512*512*128 floats = 256 MiB scratch for the fc1+gelu intermediate "h".
__device__ float g_h[2u * 512u * 512u * 128u];

__device__ __forceinline__ float leaky(float z) { return z >= 0.f ? z : 0.3f * z; }
__device__ __forceinline__ float gelu_exact(float z) {
    return 0.5f * z * (1.f + erff(z * 0.70710678118654752f));
}

// ============================================================================
// K1: LN1 + window-partition + QKV(leaky) + softmax(QK^T*scale + bias) + PV
//     + proj + shortcut residual  ->  x2 (stored into d_out as scratch)
// One block = one 8x8 window (64 tokens x 32 channels). 256 threads.
// ============================================================================
__global__ void __launch_bounds__(256) k1_attn(
    const float* __restrict__ x,
    const float* __restrict__ g1, const float* __restrict__ be1,
    const float* __restrict__ Wq, const float* __restrict__ bq,
    const float* __restrict__ Wkv, const float* __restrict__ bkv,
    const float* __restrict__ bias_table, const int* __restrict__ rel_idx,
    const float* __restrict__ Wp, const float* __restrict__ bp,
    float* __restrict__ x2)
{
    extern __shared__ float sm1[];
    float* sX   = sm1;            // 64*33 = 2112 (x, then normalized in place)
    float* sQ   = sX + 2112;      // 2112 (q*scale; later reused for attn@v)
    float* sK   = sQ + 2112;      // 2112 (k; later reused for proj output)
    float* sV   = sK + 2112;      // 2112
    float* sS   = sV + 2112;      // 64*65 = 4160 scores / probs
    float* sWq  = sS + 4160;      // 1024
    float* sWkv = sWq + 1024;     // 2048
    float* sWp  = sWkv + 2048;    // 1024
    float* sBq  = sWp + 1024;     // 32
    float* sBkv = sBq + 32;       // 64
    float* sBp  = sBkv + 64;      // 32
    float* sG1  = sBp + 32;       // 32
    float* sBe1 = sG1 + 32;       // 32

    const int tid = threadIdx.x;
    const int w   = blockIdx.x;
    const int b   = w >> 12;          // batch
    const int wr  = (w >> 6) & 63;    // window row
    const int wc  = w & 63;           // window col

    // ---- stage weights into smem ----
    for (int i = tid; i < 1024; i += 256) sWq[i] = Wq[i];
    for (int i = tid; i < 2048; i += 256) sWkv[i] = Wkv[i];
    for (int i = tid; i < 1024; i += 256) sWp[i] = Wp[i];
    if (tid < 32) { sBq[tid] = bq[tid]; sBp[tid] = bp[tid]; sG1[tid] = g1[tid]; sBe1[tid] = be1[tid]; }
    if (tid < 64) sBkv[tid] = bkv[tid];

    // ---- coalesced window load: 8 row-segments of 8 px * 32 ch = 256 floats ----
    const int iy   = tid >> 5;   // 0..7  (row within window)
    const int lane = tid & 31;
    const size_t gbase = ((size_t)b * 262144u + (size_t)(wr * 8 + iy) * 512u + (size_t)wc * 8u) * 32u;
    float4 v0 = *(const float4*)(x + gbase + lane * 8);
    float4 v1 = *(const float4*)(x + gbase + lane * 8 + 4);
    {
        int idx = lane * 8;                        // 0..248, 8-aligned within a token
        float* dst = sX + (iy * 8 + (idx >> 5)) * 33 + (idx & 31);
        dst[0] = v0.x; dst[1] = v0.y; dst[2] = v0.z; dst[3] = v0.w;
        dst[4] = v1.x; dst[5] = v1.y; dst[6] = v1.z; dst[7] = v1.w;
    }
    __syncthreads();

    // ---- LayerNorm1 per token (in place) ----
    if (tid < 64) {
        float* r = sX + tid * 33;
        float s = 0.f;
        #pragma unroll
        for (int c = 0; c < 32; c++) s += r[c];
        float m = s * (1.f / 32.f);
        float vv = 0.f;
        #pragma unroll
        for (int c = 0; c < 32; c++) { float d = r[c] - m; vv += d * d; }
        float inv = rsqrtf(vv * (1.f / 32.f) + 1e-3f);
        #pragma unroll
        for (int c = 0; c < 32; c++) r[c] = (r[c] - m) * inv * sG1[c] + sBe1[c];
    }
    __syncthreads();

    // ---- QKV: 64 tokens x 96 out-ch. thread: token = tid&63, cout = grp+4j ----
    {
        const int t = tid & 63, grp = tid >> 6;
        float acc[24];
        #pragma unroll
        for (int j = 0; j < 24; j++) {
            int cout = grp + 4 * j;
            acc[j] = (j < 8) ? sBq[cout] : sBkv[cout - 32];
        }
        for (int cin = 0; cin < 32; cin++) {
            float xv = sX[t * 33 + cin];
            #pragma unroll
            for (int j = 0; j < 24; j++) {
                int cout = grp + 4 * j;
                float wv = (j < 8) ? sWq[cin * 32 + cout] : sWkv[cin * 64 + cout - 32];
                acc[j] += xv * wv;
            }
        }
        #pragma unroll
        for (int j = 0; j < 24; j++) {
            int cout = grp + 4 * j;
            float z = leaky(acc[j]);
            if (j < 8)        sQ[t * 33 + cout]        = z * 0.17677669529663687f; // * HD^-0.5
            else if (j < 16)  sK[t * 33 + (cout - 32)] = z;
            else              sV[t * 33 + (cout - 64)] = z;
        }
    }
    __syncthreads();

    // ---- scores: s[n][m] = q[n].k[m] + bias_table[rel_idx[n][m]] ----
    {
        const int n = tid & 63, mg = tid >> 6;
        float acc[16];
        #pragma unroll
        for (int j = 0; j < 16; j++) {
            int m = mg + 4 * j;
            acc[j] = __ldg(&bias_table[__ldg(&rel_idx[n * 64 + m])]);
        }
        for (int d = 0; d < 32; d++) {
            float qv = sQ[n * 33 + d];
            #pragma unroll
            for (int j = 0; j < 16; j++) acc[j] += qv * sK[(mg + 4 * j) * 33 + d];
        }
        #pragma unroll
        for (int j = 0; j < 16; j++) sS[n * 65 + mg + 4 * j] = acc[j];
    }
    __syncthreads();

    // ---- softmax per row ----
    if (tid < 64) {
        float* r = sS + tid * 65;
        float mx = -1e30f;
        #pragma unroll
        for (int m = 0; m < 64; m++) mx = fmaxf(mx, r[m]);
        float sum = 0.f;
        #pragma unroll
        for (int m = 0; m < 64; m++) { float e = expf(r[m] - mx); r[m] = e; sum += e; }
        float inv = 1.f / sum;
        #pragma unroll
        for (int m = 0; m < 64; m++) r[m] *= inv;
    }
    __syncthreads();

    // ---- out = P @ V  (write into sQ; q no longer needed) ----
    {
        const int t = tid & 63, dg = tid >> 6;
        float acc[8] = {0.f, 0.f, 0.f, 0.f, 0.f, 0.f, 0.f, 0.f};
        for (int m = 0; m < 64; m++) {
            float pv = sS[t * 65 + m];
            #pragma unroll
            for (int j = 0; j < 8; j++) acc[j] += pv * sV[m * 33 + dg + 4 * j];
        }
        #pragma unroll
        for (int j = 0; j < 8; j++) sQ[t * 33 + dg + 4 * j] = acc[j];
    }
    __syncthreads();

    // ---- proj: out @ Wp + bp  (write into sK; k no longer needed) ----
    {
        const int t = tid & 63, cg = tid >> 6;
        float acc[8];
        #pragma unroll
        for (int j = 0; j < 8; j++) acc[j] = sBp[cg + 4 * j];
        for (int d = 0; d < 32; d++) {
            float ov = sQ[t * 33 + d];
            #pragma unroll
            for (int j = 0; j < 8; j++) acc[j] += ov * sWp[d * 32 + cg + 4 * j];
        }
        #pragma unroll
        for (int j = 0; j < 8; j++) sK[t * 33 + cg + 4 * j] = acc[j];
    }
    __syncthreads();

    // ---- x2 = shortcut(x) + window_reverse(proj); coalesced store ----
    {
        int idx = lane * 8;
        const float* srcr = sK + (iy * 8 + (idx >> 5)) * 33 + (idx & 31);
        float4 o0, o1;
        o0.x = srcr[0] + v0.x; o0.y = srcr[1] + v0.y; o0.z = srcr[2] + v0.z; o0.w = srcr[3] + v0.w;
        o1.x = srcr[4] + v1.x; o1.y = srcr[5] + v1.y; o1.z = srcr[6] + v1.z; o1.w = srcr[7] + v1.w;
        *(float4*)(x2 + gbase + lane * 8)     = o0;
        *(float4*)(x2 + gbase + lane * 8 + 4) = o1;
    }
}

// ============================================================================
// K2: h = gelu( LN2(x2) @ W1 + b1 )  -> g_h   (one warp per token)
// ============================================================================
__global__ void __launch_bounds__(256) k2_ff1(
    const float* __restrict__ x2,
    const float* __restrict__ g2, const float* __restrict__ be2,
    const float* __restrict__ W1, const float* __restrict__ b1)
{
    __shared__ float sW[4096];
    __shared__ float sB[128];
    __shared__ float sG[32], sE[32];
    const int tid = threadIdx.x;
    for (int i = tid; i < 4096; i += 256) sW[i] = W1[i];
    if (tid < 128) sB[tid] = b1[tid];
    if (tid < 32) { sG[tid] = g2[tid]; sE[tid] = be2[tid]; }
    __syncthreads();

    const int lane = tid & 31;
    const size_t tok = (size_t)blockIdx.x * 8 + (tid >> 5);
    float xv = x2[tok * 32 + lane];

    float s = xv;
    #pragma unroll
    for (int o = 16; o; o >>= 1) s += __shfl_xor_sync(FULLMASK, s, o);
    float m = s * (1.f / 32.f);
    float d = xv - m;
    float vs = d * d;
    #pragma unroll
    for (int o = 16; o; o >>= 1) vs += __shfl_xor_sync(FULLMASK, vs, o);
    float xn = d * rsqrtf(vs * (1.f / 32.f) + 1e-3f) * sG[lane] + sE[lane];

    float a0 = sB[lane], a1 = sB[lane + 32], a2 = sB[lane + 64], a3 = sB[lane + 96];
    #pragma unroll
    for (int cin = 0; cin < 32; cin++) {
        float wv = __shfl_sync(FULLMASK, xn, cin);
        const float* wr = sW + cin * 128 + lane;
        a0 += wv * wr[0]; a1 += wv * wr[32]; a2 += wv * wr[64]; a3 += wv * wr[96];
    }
    float* hp = g_h + tok * 128 + lane;
    hp[0]  = gelu_exact(a0);
    hp[32] = gelu_exact(a1);
    hp[64] = gelu_exact(a2);
    hp[96] = gelu_exact(a3);
}

// ============================================================================
// K3: depthwise 3x3 SAME conv on h + bias, gelu, @ W2 + b2, add x2 -> out
// 8x8 pixel tile per block; halo in smem; fc2 via warp shuffles.
// out pointer holds x2 on input; final result written in place.
// ============================================================================
__global__ void __launch_bounds__(256) k3_conv_ff2(
    const float* __restrict__ dwk, const float* __restrict__ dwb,
    const float* __restrict__ W2, const float* __restrict__ b2,
    float* __restrict__ out)
{
    extern __shared__ float sm3[];
    float* sH  = sm3;           // 10*10*128 = 12800
    float* sKw = sH + 12800;    // 9*128 = 1152
    float* sW2 = sKw + 1152;    // 128*32 = 4096
    float* sDb = sW2 + 4096;    // 128
    float* sB2 = sDb + 128;     // 32

    const int tid = threadIdx.x;
    const int bxx = blockIdx.x, byy = blockIdx.y, bzz = blockIdx.z;
    for (int i = tid; i < 1152; i += 256) sKw[i] = dwk[i];
    for (int i = tid; i < 4096; i += 256) sW2[i] = W2[i];
    if (tid < 128) sDb[tid] = dwb[tid];
    if (tid < 32) sB2[tid] = b2[tid];

    const int y0 = byy * 8, x0 = bxx * 8;
    for (int idx = tid; idx < 12800; idx += 256) {
        int p = idx >> 7, ch = idx & 127;
        int hy = y0 - 1 + p / 10;
        int hx = x0 - 1 + p % 10;
        float v = 0.f;
        if (hy >= 0 && hy < 512 && hx >= 0 && hx < 512)
            v = g_h[(((size_t)bzz * 512 + hy) * 512 + hx) * 128 + ch];
        sH[idx] = v;
    }
    __syncthreads();

    const int lane = tid & 31, warp = tid >> 5;
    #pragma unroll 1
    for (int pi = 0; pi < 8; pi++) {
        const int p = warp * 8 + pi;
        const int py = p >> 3, px = p & 7;
        float a[4];
        #pragma unroll
        for (int j = 0; j < 4; j++) {
            int ch = lane + 32 * j;
            float acc = sDb[ch];
            #pragma unroll
            for (int ky = 0; ky < 3; ky++)
                #pragma unroll
                for (int kx = 0; kx < 3; kx++)
                    acc += sH[((py + ky) * 10 + px + kx) * 128 + ch] * sKw[(ky * 3 + kx) * 128 + ch];
            a[j] = gelu_exact(acc);
        }
        float o = sB2[lane];
        #pragma unroll
        for (int j = 0; j < 4; j++)
            #pragma unroll
            for (int kk = 0; kk < 32; kk++) {
                float av = __shfl_sync(FULLMASK, a[j], kk);
                o += av * sW2[(j * 32 + kk) * 32 + lane];
            }
        size_t off = (((size_t)bzz * 512 + (y0 + py)) * 512 + (x0 + px)) * 32 + lane;
        out[off] += o;   // x2 + mlp_out, in place
    }
}

// ============================================================================
// launch
// ============================================================================
extern "C" void kernel_launch(void* const* d_in, const int* in_sizes, int n_in,
                              void* d_out, int out_size)
{
    const float* x          = (const float*)d_in[0];
    const float* g1         = (const float*)d_in[1];
    const float* beta1      = (const float*)d_in[2];
    const float* Wq         = (const float*)d_in[3];
    const float* bq         = (const float*)d_in[4];
    const float* Wkv        = (const float*)d_in[5];
    const float* bkv        = (const float*)d_in[6];
    const float* bias_table = (const float*)d_in[7];
    const float* Wp         = (const float*)d_in[8];
    const float* bp         = (const float*)d_in[9];
    const float* g2         = (const float*)d_in[10];
    const float* beta2      = (const float*)d_in[11];
    const float* W1         = (const float*)d_in[12];
    const float* b1m        = (const float*)d_in[13];
    const float* dw_k       = (const float*)d_in[14];
    const float* dw_b       = (const float*)d_in[15];
    const float* W2         = (const float*)d_in[16];
    const float* b2m        = (const float*)d_in[17];
    const int*   rel_idx    = (const int*)d_in[18];
    float* out = (float*)d_out;

    const int SMEM1 = 16896 * 4;   // 67584 B
    const int SMEM3 = 18208 * 4;   // 72832 B
    cudaFuncSetAttribute(k1_attn,     cudaFuncAttributeMaxDynamicSharedMemorySize, SMEM1);
    cudaFuncSetAttribute(k3_conv_ff2, cudaFuncAttributeMaxDynamicSharedMemorySize, SMEM3);

    // K1: x2 = x + attn(...)  -> stored into d_out (scratch)
    k1_attn<<<8192, 256, SMEM1>>>(x, g1, beta1, Wq, bq, Wkv, bkv,
                                  bias_table, rel_idx, Wp, bp, out);
    // K2: h = gelu(LN2(x2) @ W1 + b1)  -> g_h
    k2_ff1<<<65536, 256>>>(out, g2, beta2, W1, b1m);
    // K3: out = x2 + (gelu(dwconv(h)+db) @ W2 + b2)
    k3_conv_ff2<<<dim3(64, 64, 2), 256, SMEM3>>>(dw_k, dw_b, W2, b2m, out);
}

// round 2
// speedup vs baseline: 1.7802x; 1.7802x over previous
#include <cuda_runtime.h>
#include <math.h>

#define FULLMASK 0xFFFFFFFFu

// 2*512*512*128 floats = 256 MiB scratch for the fc1+gelu intermediate "h".
__device__ float g_h[2u * 512u * 512u * 128u];
// dense 64x64 attention bias (bias_table gathered through rel_idx)
__device__ float g_bias[64 * 64];

// ---------------- packed fp32x2 helpers (Blackwell FFMA2) ----------------
__device__ __forceinline__ unsigned long long pk2(float a, float b) {
    unsigned long long r;
    asm("mov.b64 %0, {%1,%2};" : "=l"(r) : "f"(a), "f"(b));
    return r;
}
__device__ __forceinline__ void upk2(unsigned long long v, float& a, float& b) {
    asm("mov.b64 {%0,%1}, %2;" : "=f"(a), "=f"(b) : "l"(v));
}
__device__ __forceinline__ unsigned long long ffma2(unsigned long long a,
                                                    unsigned long long b,
                                                    unsigned long long c) {
    unsigned long long d;
    asm("fma.rn.f32x2 %0, %1, %2, %3;" : "=l"(d) : "l"(a), "l"(b), "l"(c));
    return d;
}

__device__ __forceinline__ float leaky(float z) { return z >= 0.f ? z : 0.3f * z; }

__device__ __forceinline__ float rcp_fast(float x) {
    float r; asm("rcp.approx.f32 %0, %1;" : "=f"(r) : "f"(x)); return r;
}

// branch-free gelu via Abramowitz-Stegun 7.1.26 erf (abs err <= 1.5e-7)
__device__ __forceinline__ float fast_gelu(float x) {
    float u  = x * 0.70710678118654752f;
    float au = fabsf(u);
    float t  = rcp_fast(fmaf(0.3275911f, au, 1.0f));
    float p  = fmaf(1.061405429f, t, -1.453152027f);
    p = fmaf(p, t, 1.421413741f);
    p = fmaf(p, t, -0.284496736f);
    p = fmaf(p, t, 0.254829592f);
    p *= t;
    float e    = __expf(-u * u);
    float erfa = fmaf(-p, e, 1.0f);
    float erfu = copysignf(erfa, u);
    return 0.5f * x * (1.0f + erfu);
}

// ============================================================================
// K0: g_bias[n][m] = bias_table[rel_idx[n*64+m]]   (HEADS = 1)
// ============================================================================
__global__ void k0_bias(const float* __restrict__ bt, const int* __restrict__ ridx) {
    int i = blockIdx.x * 256 + threadIdx.x;   // 16*256 = 4096
    g_bias[i] = bt[ridx[i]];
}

// ============================================================================
// K1: LN1 + window QKV(leaky) + softmax(QK^T*scale + bias) + PV + proj
//     + shortcut residual -> x2 (stored into d_out as scratch)
// 256 threads = 4 windows, thread-per-token. Everything register-resident
// except k^T, v, weights, bias (smem, read as vector broadcasts).
// ============================================================================
__global__ void __launch_bounds__(256, 2) k1_attn(
    const float* __restrict__ x,
    const float* __restrict__ g1, const float* __restrict__ be1,
    const float* __restrict__ Wq, const float* __restrict__ bq,
    const float* __restrict__ Wkv, const float* __restrict__ bkv,
    const float* __restrict__ Wp, const float* __restrict__ bp,
    float* __restrict__ x2)
{
    extern __shared__ float sm[];
    float* sWq   = sm;              // 1024
    float* sWkv  = sm + 1024;       // 2048
    float* sWp   = sm + 3072;       // 1024
    float* sBias = sm + 4096;       // 64*66 = 4224
    float* sBq   = sm + 8320;       // 32
    float* sBkv  = sm + 8352;       // 64
    float* sBp   = sm + 8416;       // 32
    float* sG1   = sm + 8448;       // 32
    float* sBe1  = sm + 8480;       // 32
    // per-window: kT[32][68] = 2176, sV[64][36] = 2304  -> 4480 floats
    const int tid = threadIdx.x;
    float* winb = sm + 8512 + (tid >> 6) * 4480;
    float* kT   = winb;
    float* sV   = winb + 2176;

    const int t   = tid & 63;
    const int win = blockIdx.x * 4 + (tid >> 6);
    const int b   = win >> 12;
    const int wr  = (win >> 6) & 63;
    const int wc  = win & 63;

    // ---- stage shared data ----
    for (int i = tid; i < 1024; i += 256) sWq[i] = Wq[i];
    for (int i = tid; i < 2048; i += 256) sWkv[i] = Wkv[i];
    for (int i = tid; i < 1024; i += 256) sWp[i] = Wp[i];
    for (int i = tid; i < 4096; i += 256) sBias[(i >> 6) * 66 + (i & 63)] = g_bias[i];
    if (tid < 32) { sBq[tid] = bq[tid]; sBp[tid] = bp[tid]; sG1[tid] = g1[tid]; sBe1[tid] = be1[tid]; }
    if (tid < 64) sBkv[tid] = bkv[tid];

    // ---- load token, LN stats in registers ----
    const int py = wr * 8 + (t >> 3);
    const int px = wc * 8 + (t & 7);
    const float* xp = x + ((size_t)b * 262144u + (size_t)py * 512u + px) * 32u;
    float xv[32];
    #pragma unroll
    for (int j = 0; j < 8; j++) {
        float4 v = ((const float4*)xp)[j];
        xv[4 * j] = v.x; xv[4 * j + 1] = v.y; xv[4 * j + 2] = v.z; xv[4 * j + 3] = v.w;
    }
    float s = 0.f;
    #pragma unroll
    for (int c = 0; c < 32; c++) s += xv[c];
    float m = s * (1.f / 32.f);
    float vs = 0.f;
    #pragma unroll
    for (int c = 0; c < 32; c++) { float d = xv[c] - m; vs += d * d; }
    float inv = rsqrtf(vs * (1.f / 32.f) + 1e-3f);

    __syncthreads();

    float xn[32];
    #pragma unroll
    for (int c = 0; c < 32; c++) xn[c] = (xv[c] - m) * inv * sG1[c] + sBe1[c];

    // ---- K = leaky(xn @ Wkv[:, :32] + bkv[:32])  -> kT[d][t] ----
    {
        unsigned long long a[16];
        #pragma unroll
        for (int i = 0; i < 16; i++) a[i] = pk2(sBkv[2 * i], sBkv[2 * i + 1]);
        #pragma unroll
        for (int c = 0; c < 32; c++) {
            unsigned long long xc = pk2(xn[c], xn[c]);
            const ulonglong2* wrow = (const ulonglong2*)(sWkv + c * 64);
            #pragma unroll
            for (int j = 0; j < 8; j++) {
                ulonglong2 wv = wrow[j];
                a[2 * j]     = ffma2(xc, wv.x, a[2 * j]);
                a[2 * j + 1] = ffma2(xc, wv.y, a[2 * j + 1]);
            }
        }
        #pragma unroll
        for (int i = 0; i < 16; i++) {
            float f0, f1; upk2(a[i], f0, f1);
            kT[(2 * i) * 68 + t]     = leaky(f0);
            kT[(2 * i + 1) * 68 + t] = leaky(f1);
        }
    }
    // ---- V = leaky(xn @ Wkv[:, 32:] + bkv[32:]) -> sV[t][d] ----
    {
        unsigned long long a[16];
        #pragma unroll
        for (int i = 0; i < 16; i++) a[i] = pk2(sBkv[32 + 2 * i], sBkv[32 + 2 * i + 1]);
        #pragma unroll
        for (int c = 0; c < 32; c++) {
            unsigned long long xc = pk2(xn[c], xn[c]);
            const ulonglong2* wrow = (const ulonglong2*)(sWkv + c * 64 + 32);
            #pragma unroll
            for (int j = 0; j < 8; j++) {
                ulonglong2 wv = wrow[j];
                a[2 * j]     = ffma2(xc, wv.x, a[2 * j]);
                a[2 * j + 1] = ffma2(xc, wv.y, a[2 * j + 1]);
            }
        }
        float4* vrow = (float4*)(sV + t * 36);
        #pragma unroll
        for (int j = 0; j < 8; j++) {
            float f0, f1, f2, f3;
            upk2(a[2 * j], f0, f1); upk2(a[2 * j + 1], f2, f3);
            float4 o; o.x = leaky(f0); o.y = leaky(f1); o.z = leaky(f2); o.w = leaky(f3);
            vrow[j] = o;
        }
    }
    // ---- Q = leaky(xn @ Wq + bq) * SCALE  (registers) ----
    float q[32];
    {
        unsigned long long a[16];
        #pragma unroll
        for (int i = 0; i < 16; i++) a[i] = pk2(sBq[2 * i], sBq[2 * i + 1]);
        #pragma unroll
        for (int c = 0; c < 32; c++) {
            unsigned long long xc = pk2(xn[c], xn[c]);
            const ulonglong2* wrow = (const ulonglong2*)(sWq + c * 32);
            #pragma unroll
            for (int j = 0; j < 8; j++) {
                ulonglong2 wv = wrow[j];
                a[2 * j]     = ffma2(xc, wv.x, a[2 * j]);
                a[2 * j + 1] = ffma2(xc, wv.y, a[2 * j + 1]);
            }
        }
        #pragma unroll
        for (int i = 0; i < 16; i++) {
            float f0, f1; upk2(a[i], f0, f1);
            q[2 * i]     = leaky(f0) * 0.17677669529663687f;
            q[2 * i + 1] = leaky(f1) * 0.17677669529663687f;
        }
    }
    __syncthreads();

    // ---- scores: accs[m-pair] = bias + sum_d q[d]*kT[d][m] ----
    unsigned long long accs[32];
    {
        const float2* brow = (const float2*)(sBias + t * 66);
        #pragma unroll
        for (int i = 0; i < 32; i++) { float2 bb = brow[i]; accs[i] = pk2(bb.x, bb.y); }
        #pragma unroll
        for (int d = 0; d < 32; d++) {
            unsigned long long qd = pk2(q[d], q[d]);
            const ulonglong2* kr = (const ulonglong2*)(kT + d * 68);
            #pragma unroll
            for (int j = 0; j < 16; j++) {
                ulonglong2 kk = kr[j];
                accs[2 * j]     = ffma2(qd, kk.x, accs[2 * j]);
                accs[2 * j + 1] = ffma2(qd, kk.y, accs[2 * j + 1]);
            }
        }
    }
    // ---- softmax (registers) ----
    float pinv;
    {
        float mx = -1e30f;
        #pragma unroll
        for (int i = 0; i < 32; i++) { float a0, a1; upk2(accs[i], a0, a1); mx = fmaxf(mx, fmaxf(a0, a1)); }
        float sum = 0.f;
        #pragma unroll
        for (int i = 0; i < 32; i++) {
            float a0, a1; upk2(accs[i], a0, a1);
            float e0 = __expf(a0 - mx), e1 = __expf(a1 - mx);
            sum += e0 + e1;
            accs[i] = pk2(e0, e1);
        }
        pinv = 1.f / sum;
    }
    // ---- out = P @ V  -> packed outp over d ----
    unsigned long long outp[16];
    {
        unsigned long long z = pk2(0.f, 0.f);
        #pragma unroll
        for (int i = 0; i < 16; i++) outp[i] = z;
        #pragma unroll
        for (int i = 0; i < 32; i++) {
            float p0, p1; upk2(accs[i], p0, p1);
            p0 *= pinv; p1 *= pinv;
            unsigned long long pm0 = pk2(p0, p0);
            const ulonglong2* vr0 = (const ulonglong2*)(sV + (2 * i) * 36);
            #pragma unroll
            for (int j = 0; j < 8; j++) {
                ulonglong2 vv = vr0[j];
                outp[2 * j]     = ffma2(pm0, vv.x, outp[2 * j]);
                outp[2 * j + 1] = ffma2(pm0, vv.y, outp[2 * j + 1]);
            }
            unsigned long long pm1 = pk2(p1, p1);
            const ulonglong2* vr1 = (const ulonglong2*)(sV + (2 * i + 1) * 36);
            #pragma unroll
            for (int j = 0; j < 8; j++) {
                ulonglong2 vv = vr1[j];
                outp[2 * j]     = ffma2(pm1, vv.x, outp[2 * j]);
                outp[2 * j + 1] = ffma2(pm1, vv.y, outp[2 * j + 1]);
            }
        }
    }
    // ---- proj: accf = out @ Wp + bp ----
    unsigned long long accf[16];
    {
        #pragma unroll
        for (int i = 0; i < 16; i++) accf[i] = pk2(sBp[2 * i], sBp[2 * i + 1]);
        #pragma unroll
        for (int i = 0; i < 16; i++) {
            float o0, o1; upk2(outp[i], o0, o1);
            unsigned long long m0 = pk2(o0, o0);
            const ulonglong2* wr0 = (const ulonglong2*)(sWp + (2 * i) * 32);
            #pragma unroll
            for (int j = 0; j < 8; j++) {
                ulonglong2 wv = wr0[j];
                accf[2 * j]     = ffma2(m0, wv.x, accf[2 * j]);
                accf[2 * j + 1] = ffma2(m0, wv.y, accf[2 * j + 1]);
            }
            unsigned long long m1 = pk2(o1, o1);
            const ulonglong2* wr1 = (const ulonglong2*)(sWp + (2 * i + 1) * 32);
            #pragma unroll
            for (int j = 0; j < 8; j++) {
                ulonglong2 wv = wr1[j];
                accf[2 * j]     = ffma2(m1, wv.x, accf[2 * j]);
                accf[2 * j + 1] = ffma2(m1, wv.y, accf[2 * j + 1]);
            }
        }
    }
    // ---- x2 = shortcut + proj ----
    {
        float* op = x2 + ((size_t)b * 262144u + (size_t)py * 512u + px) * 32u;
        #pragma unroll
        for (int j = 0; j < 8; j++) {
            float4 sc = ((const float4*)xp)[j];
            float f0, f1, f2, f3;
            upk2(accf[2 * j], f0, f1); upk2(accf[2 * j + 1], f2, f3);
            float4 o; o.x = sc.x + f0; o.y = sc.y + f1; o.z = sc.z + f2; o.w = sc.w + f3;
            ((float4*)op)[j] = o;
        }
    }
}

// ============================================================================
// K2: h = gelu( LN2(x2) @ W1 + b1 )  -> g_h
// 2048 blocks x 256 thr; warp-per-token, 32 tokens per warp (looped).
// ============================================================================
__global__ void __launch_bounds__(256) k2_ff1(
    const float* __restrict__ x2,
    const float* __restrict__ g2, const float* __restrict__ be2,
    const float* __restrict__ W1, const float* __restrict__ b1)
{
    __shared__ float sW1[4096];
    __shared__ float sB1[128];
    __shared__ float sG[32], sE[32];
    __shared__ float sXn[8 * 36];
    const int tid = threadIdx.x;
    for (int i = tid; i < 4096; i += 256) sW1[i] = W1[i];
    if (tid < 128) sB1[tid] = b1[tid];
    if (tid < 32) { sG[tid] = g2[tid]; sE[tid] = be2[tid]; }
    __syncthreads();

    const int lane = tid & 31, w = tid >> 5;
    float4 bb = ((const float4*)sB1)[lane];
    float gml = sG[lane], bel = sE[lane];
    const size_t tok0 = (size_t)blockIdx.x * 256 + w * 32;

    #pragma unroll 1
    for (int it = 0; it < 32; ++it) {
        size_t tok = tok0 + it;
        float xvv = x2[tok * 32 + lane];
        float s = xvv;
        #pragma unroll
        for (int o = 16; o; o >>= 1) s += __shfl_xor_sync(FULLMASK, s, o);
        float mm = s * (1.f / 32.f);
        float dd = xvv - mm;
        float vsq = dd * dd;
        #pragma unroll
        for (int o = 16; o; o >>= 1) vsq += __shfl_xor_sync(FULLMASK, vsq, o);
        float xnv = dd * rsqrtf(vsq * (1.f / 32.f) + 1e-3f) * gml + bel;
        sXn[w * 36 + lane] = xnv;
        __syncwarp();

        unsigned long long a0 = pk2(bb.x, bb.y), a1 = pk2(bb.z, bb.w);
        #pragma unroll
        for (int c4 = 0; c4 < 8; c4++) {
            float4 xc = ((const float4*)(sXn + w * 36))[c4];
            float xs0 = xc.x, xs1 = xc.y, xs2 = xc.z, xs3 = xc.w;
            {
                unsigned long long xpk = pk2(xs0, xs0);
                ulonglong2 ww = ((const ulonglong2*)(sW1 + (c4 * 4 + 0) * 128))[lane];
                a0 = ffma2(xpk, ww.x, a0); a1 = ffma2(xpk, ww.y, a1);
            }
            {
                unsigned long long xpk = pk2(xs1, xs1);
                ulonglong2 ww = ((const ulonglong2*)(sW1 + (c4 * 4 + 1) * 128))[lane];
                a0 = ffma2(xpk, ww.x, a0); a1 = ffma2(xpk, ww.y, a1);
            }
            {
                unsigned long long xpk = pk2(xs2, xs2);
                ulonglong2 ww = ((const ulonglong2*)(sW1 + (c4 * 4 + 2) * 128))[lane];
                a0 = ffma2(xpk, ww.x, a0); a1 = ffma2(xpk, ww.y, a1);
            }
            {
                unsigned long long xpk = pk2(xs3, xs3);
                ulonglong2 ww = ((const ulonglong2*)(sW1 + (c4 * 4 + 3) * 128))[lane];
                a0 = ffma2(xpk, ww.x, a0); a1 = ffma2(xpk, ww.y, a1);
            }
        }
        float f0, f1, f2, f3;
        upk2(a0, f0, f1); upk2(a1, f2, f3);
        float4 o;
        o.x = fast_gelu(f0); o.y = fast_gelu(f1); o.z = fast_gelu(f2); o.w = fast_gelu(f3);
        ((float4*)(g_h + tok * 128))[lane] = o;
        __syncwarp();
    }
}

// ============================================================================
// K3: depthwise 3x3 + bias + gelu -> h' tile (smem) -> fc2 (f32x2 tiled GEMM)
//     out = x2 + fc2 result (in place on d_out)
// 8x8 pixel tile per block; grid (64, 64, 2).
// ============================================================================
__global__ void __launch_bounds__(256, 2) k3_conv_ff2(
    const float* __restrict__ dwk, const float* __restrict__ dwb,
    const float* __restrict__ W2, const float* __restrict__ b2,
    float* __restrict__ out)
{
    extern __shared__ float sm3[];
    float* sH  = sm3;            // 10*10*128 = 12800
    float* sHp = sH + 12800;     // 64*132   = 8448
    float* sKw = sHp + 8448;     // 1152
    float* sW2 = sKw + 1152;     // 4096
    float* sDb = sW2 + 4096;     // 128
    float* sB2 = sDb + 128;      // 32

    const int tid = threadIdx.x;
    const int bxx = blockIdx.x, byy = blockIdx.y, bzz = blockIdx.z;
    for (int i = tid; i < 288; i += 256) ((float4*)sKw)[i] = ((const float4*)dwk)[i];
    for (int i = tid; i < 1024; i += 256) ((float4*)sW2)[i] = ((const float4*)W2)[i];
    if (tid < 128) sDb[tid] = dwb[tid];
    if (tid < 32) sB2[tid] = b2[tid];

    const int y0 = byy * 8, x0 = bxx * 8;
    // halo load: 100 px * 32 float4
    for (int i = tid; i < 3200; i += 256) {
        int p = i >> 5, c4 = i & 31;
        int hy = y0 - 1 + p / 10;
        int hx = x0 - 1 + p % 10;
        float4 v = make_float4(0.f, 0.f, 0.f, 0.f);
        if (hy >= 0 && hy < 512 && hx >= 0 && hx < 512)
            v = *(const float4*)(g_h + ((size_t)((bzz * 512 + hy) * 512 + hx)) * 128u + c4 * 4);
        ((float4*)sH)[p * 32 + c4] = v;
    }
    __syncthreads();

    // depthwise conv + gelu -> sHp[tok][ch]
    {
        const int lane = tid & 31, w = tid >> 5;
        const int ch = (w & 3) * 32 + lane;
        const int rbase = (w >> 2) * 4;
        float kw[9];
        #pragma unroll
        for (int qq = 0; qq < 9; qq++) kw[qq] = sKw[qq * 128 + ch];
        const float db = sDb[ch];
        #pragma unroll
        for (int r = 0; r < 4; r++) {
            const int pyl = rbase + r;
            float A[10], Brow[10], Crow[10];
            #pragma unroll
            for (int xx = 0; xx < 10; xx++) {
                A[xx]    = sH[((pyl) * 10 + xx) * 128 + ch];
                Brow[xx] = sH[((pyl + 1) * 10 + xx) * 128 + ch];
                Crow[xx] = sH[((pyl + 2) * 10 + xx) * 128 + ch];
            }
            #pragma unroll
            for (int pxl = 0; pxl < 8; pxl++) {
                float acc = db;
                acc = fmaf(A[pxl], kw[0], acc);
                acc = fmaf(A[pxl + 1], kw[1], acc);
                acc = fmaf(A[pxl + 2], kw[2], acc);
                acc = fmaf(Brow[pxl], kw[3], acc);
                acc = fmaf(Brow[pxl + 1], kw[4], acc);
                acc = fmaf(Brow[pxl + 2], kw[5], acc);
                acc = fmaf(Crow[pxl], kw[6], acc);
                acc = fmaf(Crow[pxl + 1], kw[7], acc);
                acc = fmaf(Crow[pxl + 2], kw[8], acc);
                sHp[(pyl * 8 + pxl) * 132 + ch] = fast_gelu(acc);
            }
        }
    }
    __syncthreads();

    // fc2: 2 tok x 4 ch per thread, packed f32x2
    {
        const int tokg = tid >> 3;      // 0..31 -> tokens 2*tokg, 2*tokg+1
        const int chg  = tid & 7;       // out channels 4*chg .. 4*chg+3
        const ulonglong2 bb = ((const ulonglong2*)sB2)[chg];
        unsigned long long a00 = bb.x, a01 = bb.y, a10 = bb.x, a11 = bb.y;
        const float* h0 = sHp + (2 * tokg) * 132;
        const float* h1 = h0 + 132;
        #pragma unroll 4
        for (int k4 = 0; k4 < 32; k4++) {
            float4 ha = ((const float4*)h0)[k4];
            float4 hb = ((const float4*)h1)[k4];
            {
                ulonglong2 wv = ((const ulonglong2*)(sW2 + (4 * k4 + 0) * 32))[chg];
                unsigned long long p0 = pk2(ha.x, ha.x), p1 = pk2(hb.x, hb.x);
                a00 = ffma2(p0, wv.x, a00); a01 = ffma2(p0, wv.y, a01);
                a10 = ffma2(p1, wv.x, a10); a11 = ffma2(p1, wv.y, a11);
            }
            {
                ulonglong2 wv = ((const ulonglong2*)(sW2 + (4 * k4 + 1) * 32))[chg];
                unsigned long long p0 = pk2(ha.y, ha.y), p1 = pk2(hb.y, hb.y);
                a00 = ffma2(p0, wv.x, a00); a01 = ffma2(p0, wv.y, a01);
                a10 = ffma2(p1, wv.x, a10); a11 = ffma2(p1, wv.y, a11);
            }
            {
                ulonglong2 wv = ((const ulonglong2*)(sW2 + (4 * k4 + 2) * 32))[chg];
                unsigned long long p0 = pk2(ha.z, ha.z), p1 = pk2(hb.z, hb.z);
                a00 = ffma2(p0, wv.x, a00); a01 = ffma2(p0, wv.y, a01);
                a10 = ffma2(p1, wv.x, a10); a11 = ffma2(p1, wv.y, a11);
            }
            {
                ulonglong2 wv = ((const ulonglong2*)(sW2 + (4 * k4 + 3) * 32))[chg];
                unsigned long long p0 = pk2(ha.w, ha.w), p1 = pk2(hb.w, hb.w);
                a00 = ffma2(p0, wv.x, a00); a01 = ffma2(p0, wv.y, a01);
                a10 = ffma2(p1, wv.x, a10); a11 = ffma2(p1, wv.y, a11);
            }
        }
        // store: out += mlp
        #pragma unroll
        for (int j = 0; j < 2; j++) {
            int tok = 2 * tokg + j;
            int pyl = tok >> 3, pxl = tok & 7;
            size_t g = ((size_t)(bzz * 512 + y0 + pyl) * 512 + (x0 + pxl)) * 32u + 4 * chg;
            float4 old = *(const float4*)(out + g);
            float f0, f1, f2, f3;
            if (j == 0) { upk2(a00, f0, f1); upk2(a01, f2, f3); }
            else        { upk2(a10, f0, f1); upk2(a11, f2, f3); }
            float4 nv;
            nv.x = old.x + f0; nv.y = old.y + f1; nv.z = old.z + f2; nv.w = old.w + f3;
            *(float4*)(out + g) = nv;
        }
    }
}

// ============================================================================
// launch
// ============================================================================
extern "C" void kernel_launch(void* const* d_in, const int* in_sizes, int n_in,
                              void* d_out, int out_size)
{
    const float* x          = (const float*)d_in[0];
    const float* g1         = (const float*)d_in[1];
    const float* beta1      = (const float*)d_in[2];
    const float* Wq         = (const float*)d_in[3];
    const float* bq         = (const float*)d_in[4];
    const float* Wkv        = (const float*)d_in[5];
    const float* bkv        = (const float*)d_in[6];
    const float* bias_table = (const float*)d_in[7];
    const float* Wp         = (const float*)d_in[8];
    const float* bp         = (const float*)d_in[9];
    const float* g2         = (const float*)d_in[10];
    const float* beta2      = (const float*)d_in[11];
    const float* W1         = (const float*)d_in[12];
    const float* b1m        = (const float*)d_in[13];
    const float* dw_k       = (const float*)d_in[14];
    const float* dw_b       = (const float*)d_in[15];
    const float* W2         = (const float*)d_in[16];
    const float* b2m        = (const float*)d_in[17];
    const int*   rel_idx    = (const int*)d_in[18];
    float* out = (float*)d_out;

    const int SMEM1 = 26432 * 4;   // 105728 B
    const int SMEM3 = 26656 * 4;   // 106624 B
    cudaFuncSetAttribute(k1_attn,     cudaFuncAttributeMaxDynamicSharedMemorySize, SMEM1);
    cudaFuncSetAttribute(k3_conv_ff2, cudaFuncAttributeMaxDynamicSharedMemorySize, SMEM3);

    k0_bias<<<16, 256>>>(bias_table, rel_idx);
    k1_attn<<<2048, 256, SMEM1>>>(x, g1, beta1, Wq, bq, Wkv, bkv, Wp, bp, out);
    k2_ff1<<<2048, 256>>>(out, g2, beta2, W1, b1m);
    k3_conv_ff2<<<dim3(64, 64, 2), 256, SMEM3>>>(dw_k, dw_b, W2, b2m, out);
}